// round 1
// baseline (speedup 1.0000x reference)
#include <cuda_runtime.h>
#include <cuda_bf16.h>

// Dead-code-eliminated Net2 BSDE recurrence.
//
// The reference returns only u_f. u's recurrence is:
//   u_{k+1} = u_k - f(u_k)*dt_k + dot(gu, noise[k,:,0]) * sqrt(dt_k)
// with gu = 0.2 * x0 * gu0[:,0] constant. x and all 40 per-step MLPs are dead
// w.r.t. the output, so we compute neither.
//
// Input order (setup_inputs): x0(100), tlist(40), noise(40*100), u0(1),
// gu0(100), W1,b1,W2,b2,W3,b3 (unused).

#define D_DIM   100
#define N_STEPS 40
#define NWARPS  8
#define NTHREADS (NWARPS * 32)

__device__ __forceinline__ float drift_f(float u) {
    // Faithful translation of the piecewise drift (same constants/order).
    if (u < 50.0f) {
        return -0.02f * u / 3.0f - 0.02f * u;
    } else if (u >= 70.0f) {
        return -0.002f * u / 3.0f - 0.02f * u;
    } else {
        return -(70.0f - 50.0f) / (0.02f - 0.2f) * (u - 50.0f) / 3.0f * u
               - 0.2f / 3.0f * u - 0.02f * u;
    }
}

__global__ void net2_u_kernel(const float* __restrict__ x0,
                              const float* __restrict__ tlist,
                              const float* __restrict__ noise,   // (N_STEPS, D, 1)
                              const float* __restrict__ u0,
                              const float* __restrict__ gu0,     // (D, 1)
                              float* __restrict__ out) {
    __shared__ float term3[N_STEPS];

    const int tid  = threadIdx.x;
    const int warp = tid >> 5;
    const int lane = tid & 31;

    // Each warp computes dot(gu, dW_k) for its assigned steps.
    for (int k = warp; k < N_STEPS; k += NWARPS) {
        float s = 0.0f;
        const float* nk = noise + k * D_DIM;
        #pragma unroll
        for (int i = lane; i < D_DIM; i += 32) {
            float gu_i = 0.2f * x0[i] * gu0[i];
            s += gu_i * nk[i];
        }
        // warp reduction
        #pragma unroll
        for (int off = 16; off > 0; off >>= 1)
            s += __shfl_down_sync(0xFFFFFFFFu, s, off);
        if (lane == 0)
            term3[k] = s * sqrtf(tlist[k]);
    }
    __syncthreads();

    if (tid == 0) {
        float u = u0[0];
        #pragma unroll
        for (int k = 0; k < N_STEPS; k++) {
            float dt = tlist[k];
            u = u - drift_f(u) * dt + term3[k];
        }
        out[0] = u;
    }
}

extern "C" void kernel_launch(void* const* d_in, const int* in_sizes, int n_in,
                              void* d_out, int out_size) {
    const float* x0    = (const float*)d_in[0];
    const float* tlist = (const float*)d_in[1];
    const float* noise = (const float*)d_in[2];
    const float* u0    = (const float*)d_in[3];
    const float* gu0   = (const float*)d_in[4];
    float* out = (float*)d_out;

    net2_u_kernel<<<1, NTHREADS>>>(x0, tlist, noise, u0, gu0, out);
}